// round 10
// baseline (speedup 1.0000x reference)
#include <cuda_runtime.h>
#include <cuda_bf16.h>
#include <cstddef>

// Problem constants
#define Bb   32
#define Nn   100
#define Hh   128
#define BINc 16
#define Ee   20000

// Scratch (device globals: no allocation allowed)
__device__ float g_P[Bb * Nn * Hh];   // L @ W_apair           (1.6 MB)
__device__ float g_S[Bb * Nn * Nn];   // att_score             (1.28 MB)
__device__ float g_G[Bb * Nn * Hh];   // global_feats          (1.6 MB)
__device__ int   g_is32;              // sparse_idx dtype flag

// ---------------- f32x2 packed-FMA helpers (FFMA2; PTX-only path) ----------
__device__ __forceinline__ unsigned long long pk2(float lo, float hi) {
    unsigned long long r;
    asm("mov.b64 %0, {%1, %2};" : "=l"(r) : "f"(lo), "f"(hi));
    return r;
}
__device__ __forceinline__ void upk2(unsigned long long v, float& lo, float& hi) {
    asm("mov.b64 {%0, %1}, %2;" : "=f"(lo), "=f"(hi) : "l"(v));
}
__device__ __forceinline__ void fma2(unsigned long long& d,
                                     unsigned long long a,
                                     unsigned long long b) {
    asm("fma.rn.f32x2 %0, %1, %2, %0;" : "+l"(d) : "l"(a), "l"(b));
}
__device__ __forceinline__ unsigned long long add2(unsigned long long a,
                                                   unsigned long long b) {
    unsigned long long r;
    asm("add.rn.f32x2 %0, %1, %2;" : "=l"(r) : "l"(a), "l"(b));
    return r;
}

// ---------------- dtype detection for sparse_idx ---------------------------
// View the index buffer as int32 words. If stored int64: every odd word is the
// high half of a value in [0,32) => all zero. If int32: odd words are random
// values in [0,32) => some nonzero with overwhelming probability over 30000
// samples (P(all zero) = 32^-30000). Must be GLOBAL (a per-edge test misfires
// w.p. ~32^-3 per edge under int32 storage). Single block: reset -> sync ->
// scan -> one write. Deterministic per input.
__global__ void kDetect(const int* __restrict__ si) {
    if (threadIdx.x == 0) g_is32 = 0;
    __syncthreads();
    int found = 0;
    for (int i = threadIdx.x; i < 30000; i += blockDim.x) {
        found |= (si[2 * i + 1] != 0);   // max index 59999 < E*3 = 60000
    }
    if (__syncthreads_or(found)) {
        if (threadIdx.x == 0) g_is32 = 1;
    }
}

// ---------------- Kernel 1: P[b,n,k] = sum_h L[b,n,h] * W_apair[h,k] -------
// 128 blocks x 128 threads; each block owns 25 contiguous (b,n) rows.
__global__ void kProj(const float* __restrict__ L, const float* __restrict__ Wa) {
    __shared__ float sL[25 * Hh];
    const int r0 = blockIdx.x * 25;  // flattened row base (b*N+n)
    for (int idx = threadIdx.x; idx < 25 * Hh; idx += 128)
        sL[idx] = L[(size_t)r0 * Hh + idx];
    __syncthreads();

    const int k = threadIdx.x;
    float acc[25];
#pragma unroll
    for (int n = 0; n < 25; n++) acc[n] = 0.f;

    for (int h = 0; h < Hh; h++) {
        const float w = Wa[h * Hh + k];  // coalesced across threads
#pragma unroll
        for (int n = 0; n < 25; n++)
            acc[n] = fmaf(sL[n * Hh + h], w, acc[n]);  // smem broadcast
    }
#pragma unroll
    for (int n = 0; n < 25; n++)
        g_P[(size_t)(r0 + n) * Hh + k] = acc[n];
}

// ---------------- Kernel 2: att_score (dominant) ---------------------------
// Grid = B*N (one block per (b,i)), 128 threads = 4 warps.
// Each warp handles 25 j values; each lane owns k = 4*lane..4*lane+3.
// W_binary columns live in packed f32x2 registers, amortized over all j.
// 4 independent FFMA2 chains saturate the FMA pipe from one warp (lat4/rt2).
// Next-j loads are software-prefetched to hide ~240-cyc L2 latency behind
// the ~170-cycle FFMA2 body (only 3 warps/SMSP at this occupancy).
// Register budget: ~64 (weights) + ~84 live temps; bounds(128,3) caps at 170.
__global__ void __launch_bounds__(128, 3)
kScores(const float* __restrict__ binf, const float* __restrict__ Wb,
        const float* __restrict__ bb, const float* __restrict__ Watt,
        const float* __restrict__ batt) {
    const int bi   = blockIdx.x;          // b*N + i
    const int b    = bi / Nn;
    const int lane = threadIdx.x & 31;
    const int warp = threadIdx.x >> 5;

    // Per-lane packed weight columns: 16 c-rows x 4 k's -> 32 u64 regs
    unsigned long long w01[BINc], w23[BINc];
#pragma unroll
    for (int c = 0; c < BINc; c++) {
        const float4 w = reinterpret_cast<const float4*>(Wb + c * Hh)[lane];
        w01[c] = pk2(w.x, w.y);
        w23[c] = pk2(w.z, w.w);
    }
    const float4 bbv = reinterpret_cast<const float4*>(bb)[lane];
    const float4 wa  = reinterpret_cast<const float4*>(Watt)[lane];
    const float  ba  = batt[0];

    const float4 pi = reinterpret_cast<const float4*>(g_P + (size_t)bi * Hh)[lane];
    const float pbx = pi.x + bbv.x, pby = pi.y + bbv.y;
    const float pbz = pi.z + bbv.z, pbw = pi.w + bbv.w;

    const float4* Prow = reinterpret_cast<const float4*>(g_P + (size_t)b * Nn * Hh);
    const float4* Brow = reinterpret_cast<const float4*>(binf + (size_t)bi * Nn * BINc);

    // Prologue: issue loads for first j
    float4 pj = Prow[(size_t)warp * 32 + lane];
    float4 c0 = Brow[warp * 4 + 0], c1 = Brow[warp * 4 + 1];
    float4 c2 = Brow[warp * 4 + 2], c3 = Brow[warp * 4 + 3];

    for (int j = warp; j < Nn; j += 4) {
        // Prefetch next iteration's data before consuming current
        const int jn = j + 4;
        float4 pjn = make_float4(0.f, 0.f, 0.f, 0.f);
        float4 c0n = pjn, c1n = pjn, c2n = pjn, c3n = pjn;
        if (jn < Nn) {
            pjn = Prow[(size_t)jn * 32 + lane];
            c0n = Brow[jn * 4 + 0]; c1n = Brow[jn * 4 + 1];
            c2n = Brow[jn * 4 + 2]; c3n = Brow[jn * 4 + 3];
        }

        const float bv[BINc] = {c0.x, c0.y, c0.z, c0.w, c1.x, c1.y, c1.z, c1.w,
                                c2.x, c2.y, c2.z, c2.w, c3.x, c3.y, c3.z, c3.w};

        // 4 independent chains: even/odd halves of c per accumulator pair.
        unsigned long long a01a = pk2(pbx + pj.x, pby + pj.y);
        unsigned long long a23a = pk2(pbz + pj.z, pbw + pj.w);
        unsigned long long a01b = pk2(0.f, 0.f);
        unsigned long long a23b = pk2(0.f, 0.f);
#pragma unroll
        for (int c = 0; c < BINc; c += 2) {
            const unsigned long long bc0 = pk2(bv[c], bv[c]);
            const unsigned long long bc1 = pk2(bv[c + 1], bv[c + 1]);
            fma2(a01a, bc0, w01[c]);
            fma2(a23a, bc0, w23[c]);
            fma2(a01b, bc1, w01[c + 1]);
            fma2(a23b, bc1, w23[c + 1]);
        }
        const unsigned long long a01 = add2(a01a, a01b);
        const unsigned long long a23 = add2(a23a, a23b);

        float ax, ay, az, aw2;
        upk2(a01, ax, ay);
        upk2(a23, az, aw2);
        ax = fmaxf(ax, 0.f); ay = fmaxf(ay, 0.f);
        az = fmaxf(az, 0.f); aw2 = fmaxf(aw2, 0.f);

        float s = ax * wa.x + ay * wa.y + az * wa.z + aw2 * wa.w;
#pragma unroll
        for (int off = 16; off > 0; off >>= 1)
            s += __shfl_xor_sync(0xffffffffu, s, off);

        if (lane == 0)
            g_S[(size_t)bi * Nn + j] = 1.f / (1.f + expf(-(s + ba)));

        pj = pjn; c0 = c0n; c1 = c1n; c2 = c2n; c3 = c3n;
    }
}

// ---------------- Kernel 3: G[b,i,h] = sum_j S[b,i,j] * L[b,j,h] -----------
// 320 blocks: each handles one b and 10 i-rows; thread = h.
__global__ void kGlob(const float* __restrict__ L) {
    __shared__ float sS[10 * Nn];
    const int b  = blockIdx.x / 10;
    const int i0 = (blockIdx.x % 10) * 10;
    for (int idx = threadIdx.x; idx < 10 * Nn; idx += 128)
        sS[idx] = g_S[((size_t)b * Nn + i0) * Nn + idx];
    __syncthreads();

    const int h = threadIdx.x;
    float acc[10];
#pragma unroll
    for (int t = 0; t < 10; t++) acc[t] = 0.f;

    for (int j = 0; j < Nn; j++) {
        const float l = L[((size_t)b * Nn + j) * Hh + h];  // coalesced
#pragma unroll
        for (int t = 0; t < 10; t++)
            acc[t] = fmaf(sS[t * Nn + j], l, acc[t]);      // smem broadcast
    }
#pragma unroll
    for (int t = 0; t < 10; t++)
        g_G[((size_t)b * Nn + i0 + t) * Hh + h] = acc[t];
}

// ---------------- Kernel 4: sparse gather + pair sums ----------------------
// Warp per edge e (32 threads = 32 float4 = 128 floats per row).
// Index loads are warp-uniform -> broadcast; row loads hit L2 (3.2 MB live).
// Output order: [local_pair_g (E,H)] then [global_pair (E,H)].
__global__ void kGather(const void* __restrict__ sp, const float* __restrict__ L,
                        float* __restrict__ out) {
    const int t = blockIdx.x * blockDim.x + threadIdx.x;
    const int total = Ee * 32;
    if (t >= total) return;
    const int e = t >> 5;
    const int q = t & 31;

    int b, i, j;
    if (g_is32) {
        const int* s = reinterpret_cast<const int*>(sp);
        b = s[3 * e]; i = s[3 * e + 1]; j = s[3 * e + 2];
    } else {
        const long long* s = reinterpret_cast<const long long*>(sp);
        b = (int)s[3 * e]; i = (int)s[3 * e + 1]; j = (int)s[3 * e + 2];
    }

    const float4* L4 = reinterpret_cast<const float4*>(L);
    const float4* G4 = reinterpret_cast<const float4*>(g_G);
    const size_t ri = (size_t)(b * Nn + i) * 32;
    const size_t rj = (size_t)(b * Nn + j) * 32;

    float4* O = reinterpret_cast<float4*>(out);

    const float4 a = L4[ri + q], c = L4[rj + q];
    float4 o;
    o.x = a.x + c.x; o.y = a.y + c.y; o.z = a.z + c.z; o.w = a.w + c.w;
    O[(size_t)e * 32 + q] = o;

    const float4 ga = G4[ri + q], gc = G4[rj + q];
    float4 og;
    og.x = ga.x + gc.x; og.y = ga.y + gc.y;
    og.z = ga.z + gc.z; og.w = ga.w + gc.w;
    O[(size_t)Ee * 32 + (size_t)e * 32 + q] = og;
}

// ---------------- launch ---------------------------------------------------
extern "C" void kernel_launch(void* const* d_in, const int* in_sizes, int n_in,
                              void* d_out, int out_size) {
    const float* L    = (const float*)d_in[0];  // (B,N,H)
    const float* binf = (const float*)d_in[1];  // (B,N,N,BIN)
    const void*  sp   = d_in[2];                // (E,3) int32 or int64
    const float* Wa   = (const float*)d_in[3];  // (H,H)
    const float* Wb   = (const float*)d_in[4];  // (BIN,H)
    const float* bb   = (const float*)d_in[5];  // (H,)
    const float* Watt = (const float*)d_in[6];  // (H,1)
    const float* ba   = (const float*)d_in[7];  // (1,)

    kDetect<<<1, 1024>>>((const int*)sp);
    kProj<<<128, 128>>>(L, Wa);
    kScores<<<Bb * Nn, 128>>>(binf, Wb, bb, Watt, ba);
    kGlob<<<Bb * 10, 128>>>(L);
    kGather<<<(Ee * 32 + 255) / 256, 256>>>(sp, L, (float*)d_out);
}

// round 12
// speedup vs baseline: 1.3128x; 1.3128x over previous
#include <cuda_runtime.h>
#include <cuda_bf16.h>
#include <cstddef>

// Problem constants
#define Bb   32
#define Nn   100
#define Hh   128
#define BINc 16
#define Ee   20000

// Scratch (device globals: no allocation allowed)
__device__ float g_P[Bb * Nn * Hh];   // L @ W_apair           (1.6 MB)
__device__ float g_S[Bb * Nn * Nn];   // att_score             (1.28 MB)
__device__ float g_G[Bb * Nn * Hh];   // global_feats          (1.6 MB)
__device__ int   g_is32;              // sparse_idx dtype flag

// ---------------- f32x2 packed-FMA helpers (FFMA2; PTX-only path) ----------
__device__ __forceinline__ unsigned long long pk2(float lo, float hi) {
    unsigned long long r;
    asm("mov.b64 %0, {%1, %2};" : "=l"(r) : "f"(lo), "f"(hi));
    return r;
}
__device__ __forceinline__ void upk2(unsigned long long v, float& lo, float& hi) {
    asm("mov.b64 {%0, %1}, %2;" : "=f"(lo), "=f"(hi) : "l"(v));
}
__device__ __forceinline__ void fma2(unsigned long long& d,
                                     unsigned long long a,
                                     unsigned long long b) {
    asm("fma.rn.f32x2 %0, %1, %2, %0;" : "+l"(d) : "l"(a), "l"(b));
}

// ---------------- dtype detection for sparse_idx ---------------------------
// int64 storage => odd int32 words all zero; int32 => nonzero w.h.p.
__global__ void kDetect(const int* __restrict__ si) {
    if (threadIdx.x == 0) g_is32 = 0;
    __syncthreads();
    int found = 0;
    for (int i = threadIdx.x; i < 30000; i += blockDim.x) {
        found |= (si[2 * i + 1] != 0);   // max index 59999 < E*3 = 60000
    }
    if (__syncthreads_or(found)) {
        if (threadIdx.x == 0) g_is32 = 1;
    }
}

// ---------------- Kernel 1: P[b,n,k] = sum_h L[b,n,h] * W_apair[h,k] -------
// 128 blocks x 128 threads; h-loop unrolled x4 for load MLP.
__global__ void kProj(const float* __restrict__ L, const float* __restrict__ Wa) {
    __shared__ float sL[25 * Hh];
    const int r0 = blockIdx.x * 25;  // flattened row base (b*N+n)
    for (int idx = threadIdx.x; idx < 25 * Hh; idx += 128)
        sL[idx] = L[(size_t)r0 * Hh + idx];
    __syncthreads();

    const int k = threadIdx.x;
    float acc[25];
#pragma unroll
    for (int n = 0; n < 25; n++) acc[n] = 0.f;

    for (int h = 0; h < Hh; h += 4) {
        const float w0 = Wa[(h + 0) * Hh + k];   // 4 independent coalesced LDGs
        const float w1 = Wa[(h + 1) * Hh + k];
        const float w2 = Wa[(h + 2) * Hh + k];
        const float w3 = Wa[(h + 3) * Hh + k];
#pragma unroll
        for (int n = 0; n < 25; n++) {
            float a = fmaf(sL[n * Hh + h + 0], w0, acc[n]);
            a       = fmaf(sL[n * Hh + h + 1], w1, a);
            a       = fmaf(sL[n * Hh + h + 2], w2, a);
            acc[n]  = fmaf(sL[n * Hh + h + 3], w3, a);
        }
    }
#pragma unroll
    for (int n = 0; n < 25; n++)
        g_P[(size_t)(r0 + n) * Hh + k] = acc[n];
}

// ---------------- Kernel 2: att_score (dominant) ---------------------------
// Grid = B*N, 128 threads = 4 warps; warp handles j = warp, warp+4, ... (25).
// TWO j's per loop iteration: 10 independent LDGs (MLP=10), 4 independent
// FFMA2 chains (2 per j), and two interleaved shfl-reduce chains.
__global__ void __launch_bounds__(128, 3)
kScores(const float* __restrict__ binf, const float* __restrict__ Wb,
        const float* __restrict__ bb, const float* __restrict__ Watt,
        const float* __restrict__ batt) {
    const int bi   = blockIdx.x;          // b*N + i
    const int b    = bi / Nn;
    const int lane = threadIdx.x & 31;
    const int warp = threadIdx.x >> 5;

    // Per-lane packed weight columns: 16 c-rows x 4 k's -> 32 u64 regs
    unsigned long long w01[BINc], w23[BINc];
#pragma unroll
    for (int c = 0; c < BINc; c++) {
        const float4 w = reinterpret_cast<const float4*>(Wb + c * Hh)[lane];
        w01[c] = pk2(w.x, w.y);
        w23[c] = pk2(w.z, w.w);
    }
    const float4 bbv = reinterpret_cast<const float4*>(bb)[lane];
    const float4 wa  = reinterpret_cast<const float4*>(Watt)[lane];
    const float  ba  = batt[0];

    const float4 pi = reinterpret_cast<const float4*>(g_P + (size_t)bi * Hh)[lane];
    const float pbx = pi.x + bbv.x, pby = pi.y + bbv.y;
    const float pbz = pi.z + bbv.z, pbw = pi.w + bbv.w;

    const float4* Prow = reinterpret_cast<const float4*>(g_P + (size_t)b * Nn * Hh);
    const float4* Brow = reinterpret_cast<const float4*>(binf + (size_t)bi * Nn * BINc);

    int j = warp;
    for (; j + 4 < Nn; j += 8) {
        const int j2 = j + 4;
        // 10 independent loads up front
        const float4 pj1 = Prow[(size_t)j  * 32 + lane];
        const float4 pj2 = Prow[(size_t)j2 * 32 + lane];
        const float4 d0 = Brow[j  * 4 + 0], d1 = Brow[j  * 4 + 1];
        const float4 d2 = Brow[j  * 4 + 2], d3 = Brow[j  * 4 + 3];
        const float4 e0 = Brow[j2 * 4 + 0], e1 = Brow[j2 * 4 + 1];
        const float4 e2 = Brow[j2 * 4 + 2], e3 = Brow[j2 * 4 + 3];

        const float bv1[BINc] = {d0.x, d0.y, d0.z, d0.w, d1.x, d1.y, d1.z, d1.w,
                                 d2.x, d2.y, d2.z, d2.w, d3.x, d3.y, d3.z, d3.w};
        const float bv2[BINc] = {e0.x, e0.y, e0.z, e0.w, e1.x, e1.y, e1.z, e1.w,
                                 e2.x, e2.y, e2.z, e2.w, e3.x, e3.y, e3.z, e3.w};

        unsigned long long a01x = pk2(pbx + pj1.x, pby + pj1.y);
        unsigned long long a23x = pk2(pbz + pj1.z, pbw + pj1.w);
        unsigned long long a01y = pk2(pbx + pj2.x, pby + pj2.y);
        unsigned long long a23y = pk2(pbz + pj2.z, pbw + pj2.w);
#pragma unroll
        for (int c = 0; c < BINc; c++) {
            const unsigned long long bc1 = pk2(bv1[c], bv1[c]);
            const unsigned long long bc2 = pk2(bv2[c], bv2[c]);
            fma2(a01x, bc1, w01[c]);
            fma2(a23x, bc1, w23[c]);
            fma2(a01y, bc2, w01[c]);
            fma2(a23y, bc2, w23[c]);
        }

        float x0, x1, x2, x3, y0, y1, y2, y3;
        upk2(a01x, x0, x1); upk2(a23x, x2, x3);
        upk2(a01y, y0, y1); upk2(a23y, y2, y3);
        x0 = fmaxf(x0, 0.f); x1 = fmaxf(x1, 0.f);
        x2 = fmaxf(x2, 0.f); x3 = fmaxf(x3, 0.f);
        y0 = fmaxf(y0, 0.f); y1 = fmaxf(y1, 0.f);
        y2 = fmaxf(y2, 0.f); y3 = fmaxf(y3, 0.f);

        float s1 = x0 * wa.x + x1 * wa.y + x2 * wa.z + x3 * wa.w;
        float s2 = y0 * wa.x + y1 * wa.y + y2 * wa.z + y3 * wa.w;
#pragma unroll
        for (int off = 16; off > 0; off >>= 1) {   // two independent chains
            s1 += __shfl_xor_sync(0xffffffffu, s1, off);
            s2 += __shfl_xor_sync(0xffffffffu, s2, off);
        }
        if (lane == 0) {
            g_S[(size_t)bi * Nn + j]  = 1.f / (1.f + __expf(-(s1 + ba)));
            g_S[(size_t)bi * Nn + j2] = 1.f / (1.f + __expf(-(s2 + ba)));
        }
    }
    if (j < Nn) {   // tail: single j
        const float4 pj1 = Prow[(size_t)j * 32 + lane];
        const float4 d0 = Brow[j * 4 + 0], d1 = Brow[j * 4 + 1];
        const float4 d2 = Brow[j * 4 + 2], d3 = Brow[j * 4 + 3];
        const float bv1[BINc] = {d0.x, d0.y, d0.z, d0.w, d1.x, d1.y, d1.z, d1.w,
                                 d2.x, d2.y, d2.z, d2.w, d3.x, d3.y, d3.z, d3.w};
        unsigned long long a01x = pk2(pbx + pj1.x, pby + pj1.y);
        unsigned long long a23x = pk2(pbz + pj1.z, pbw + pj1.w);
#pragma unroll
        for (int c = 0; c < BINc; c++) {
            const unsigned long long bc1 = pk2(bv1[c], bv1[c]);
            fma2(a01x, bc1, w01[c]);
            fma2(a23x, bc1, w23[c]);
        }
        float x0, x1, x2, x3;
        upk2(a01x, x0, x1); upk2(a23x, x2, x3);
        x0 = fmaxf(x0, 0.f); x1 = fmaxf(x1, 0.f);
        x2 = fmaxf(x2, 0.f); x3 = fmaxf(x3, 0.f);
        float s1 = x0 * wa.x + x1 * wa.y + x2 * wa.z + x3 * wa.w;
#pragma unroll
        for (int off = 16; off > 0; off >>= 1)
            s1 += __shfl_xor_sync(0xffffffffu, s1, off);
        if (lane == 0)
            g_S[(size_t)bi * Nn + j] = 1.f / (1.f + __expf(-(s1 + ba)));
    }
}

// ---------------- Kernel 3: G[b,i,h] = sum_j S[b,i,j] * L[b,j,h] -----------
// 640 blocks (b, 5 i-rows each); j-loop unrolled x4 -> MLP=4 on L loads.
__global__ void kGlob(const float* __restrict__ L) {
    __shared__ float sS[5 * Nn];
    const int b  = blockIdx.x / 20;
    const int i0 = (blockIdx.x % 20) * 5;
    for (int idx = threadIdx.x; idx < 5 * Nn; idx += 128)
        sS[idx] = g_S[((size_t)b * Nn + i0) * Nn + idx];
    __syncthreads();

    const int h = threadIdx.x;
    const float* Lb = L + (size_t)b * Nn * Hh + h;
    float acc[5];
#pragma unroll
    for (int t = 0; t < 5; t++) acc[t] = 0.f;

    for (int j = 0; j < Nn; j += 4) {      // 100 % 4 == 0, no tail
        const float l0 = Lb[(j + 0) * Hh];  // 4 independent coalesced LDGs
        const float l1 = Lb[(j + 1) * Hh];
        const float l2 = Lb[(j + 2) * Hh];
        const float l3 = Lb[(j + 3) * Hh];
#pragma unroll
        for (int t = 0; t < 5; t++) {
            float a = fmaf(sS[t * Nn + j + 0], l0, acc[t]);
            a       = fmaf(sS[t * Nn + j + 1], l1, a);
            a       = fmaf(sS[t * Nn + j + 2], l2, a);
            acc[t]  = fmaf(sS[t * Nn + j + 3], l3, a);
        }
    }
#pragma unroll
    for (int t = 0; t < 5; t++)
        g_G[((size_t)b * Nn + i0 + t) * Hh + h] = acc[t];
}

// ---------------- Kernel 4: sparse gather + pair sums ----------------------
// Warp per edge e; float4 per lane. Output: [local_pair_g | global_pair].
__global__ void kGather(const void* __restrict__ sp, const float* __restrict__ L,
                        float* __restrict__ out) {
    const int t = blockIdx.x * blockDim.x + threadIdx.x;
    const int total = Ee * 32;
    if (t >= total) return;
    const int e = t >> 5;
    const int q = t & 31;

    int b, i, j;
    if (g_is32) {
        const int* s = reinterpret_cast<const int*>(sp);
        b = s[3 * e]; i = s[3 * e + 1]; j = s[3 * e + 2];
    } else {
        const long long* s = reinterpret_cast<const long long*>(sp);
        b = (int)s[3 * e]; i = (int)s[3 * e + 1]; j = (int)s[3 * e + 2];
    }

    const float4* L4 = reinterpret_cast<const float4*>(L);
    const float4* G4 = reinterpret_cast<const float4*>(g_G);
    const size_t ri = (size_t)(b * Nn + i) * 32;
    const size_t rj = (size_t)(b * Nn + j) * 32;

    float4* O = reinterpret_cast<float4*>(out);

    const float4 a = L4[ri + q], c = L4[rj + q];
    float4 o;
    o.x = a.x + c.x; o.y = a.y + c.y; o.z = a.z + c.z; o.w = a.w + c.w;
    O[(size_t)e * 32 + q] = o;

    const float4 ga = G4[ri + q], gc = G4[rj + q];
    float4 og;
    og.x = ga.x + gc.x; og.y = ga.y + gc.y;
    og.z = ga.z + gc.z; og.w = ga.w + gc.w;
    O[(size_t)Ee * 32 + (size_t)e * 32 + q] = og;
}

// ---------------- launch ---------------------------------------------------
extern "C" void kernel_launch(void* const* d_in, const int* in_sizes, int n_in,
                              void* d_out, int out_size) {
    const float* L    = (const float*)d_in[0];  // (B,N,H)
    const float* binf = (const float*)d_in[1];  // (B,N,N,BIN)
    const void*  sp   = d_in[2];                // (E,3) int32 or int64
    const float* Wa   = (const float*)d_in[3];  // (H,H)
    const float* Wb   = (const float*)d_in[4];  // (BIN,H)
    const float* bb   = (const float*)d_in[5];  // (H,)
    const float* Watt = (const float*)d_in[6];  // (H,1)
    const float* ba   = (const float*)d_in[7];  // (1,)

    kDetect<<<1, 1024>>>((const int*)sp);
    kProj<<<128, 128>>>(L, Wa);
    kScores<<<Bb * Nn, 128>>>(binf, Wb, bb, Watt, ba);
    kGlob<<<Bb * 20, 128>>>(L);
    kGather<<<(Ee * 32 + 255) / 256, 256>>>(sp, L, (float*)d_out);
}